// round 5
// baseline (speedup 1.0000x reference)
#include <cuda_runtime.h>
#include <math.h>

#define B_      2
#define S_      1024
#define DIN     2048
#define DOUT    2048
#define H_      8
#define DK_     64
#define DV_     128
#define CONVDIM 2560
#define GDIM    1024
#define HTOT    3584   /* CONVDIM + GDIM */
#define MTOT    2048   /* B_*S_ */
#define BH_     16     /* B_*H_ */
#define KGROUPS 16     /* DK_/4 : 4 k-rows per scan block */

/* ------------------------------------------------------------------ */
__device__ float g_h [MTOT * HTOT];
__device__ float g_q [BH_ * S_ * DK_];
__device__ float g_k [BH_ * S_ * DK_];
__device__ float g_g [BH_ * S_ * DK_];
__device__ float g_v [BH_ * S_ * DV_];
__device__ float g_yp[KGROUPS * BH_ * S_ * DV_];
__device__ float g_y2[MTOT * GDIM];

__device__ __forceinline__ float sigmoidf_(float x) { return 1.f / (1.f + expf(-x)); }

__device__ __forceinline__ unsigned tf32_(float x) {
    unsigned r;
    asm("cvt.rna.tf32.f32 %0, %1;" : "=r"(r) : "f"(x));
    return r;
}

/* packed f32x2 helpers */
__device__ __forceinline__ unsigned long long fma2_(unsigned long long a,
                                                    unsigned long long b,
                                                    unsigned long long c) {
    unsigned long long d;
    asm("fma.rn.f32x2 %0, %1, %2, %3;" : "=l"(d) : "l"(a), "l"(b), "l"(c));
    return d;
}
__device__ __forceinline__ unsigned long long add2_(unsigned long long a,
                                                    unsigned long long b) {
    unsigned long long d;
    asm("add.rn.f32x2 %0, %1, %2;" : "=l"(d) : "l"(a), "l"(b));
    return d;
}
__device__ __forceinline__ unsigned long long pack2_(float lo, float hi) {
    unsigned long long d;
    asm("mov.b64 %0, {%1, %2};" : "=l"(d) : "f"(lo), "f"(hi));
    return d;
}
__device__ __forceinline__ float hsum2_(unsigned long long a) {
    float lo, hi;
    asm("mov.b64 {%0, %1}, %2;" : "=f"(lo), "=f"(hi) : "l"(a));
    return lo + hi;
}
__device__ __forceinline__ float tanh_fast_(float x) {
    float r;
    asm("tanh.approx.f32 %0, %1;" : "=f"(r) : "f"(x));
    return r;
}

/* ------------------------------------------------------------------ */
/* TF32 tensor-core GEMM (NT), 2-stage smem pipeline, 1 sync/k-tile   */
/* C[M,N] = A[M,K]*B[N,K]^T (+bias). 128x128 tile, BK=32, 256 thr.    */
/* ------------------------------------------------------------------ */
#define GPITCH 36
#define GBUF   (128 * GPITCH)          /* 4608 unsigned per buffer   */
#define GEMM_SMEM (4 * GBUF * 4)       /* 73728 bytes                */

__global__ void __launch_bounds__(256)
gemm_tf32(const float* __restrict__ A, const float* __restrict__ B,
          const float* __restrict__ bias, float* __restrict__ C,
          int M, int N, int K, int hasBias)
{
    extern __shared__ unsigned smemU[];
    unsigned* AsB = smemU;             /* 2 buffers */
    unsigned* BsB = smemU + 2 * GBUF;  /* 2 buffers */

    const int tid  = threadIdx.x;
    const int lane = tid & 31;
    const int wid  = tid >> 5;
    const int warpM = wid & 1;
    const int warpN = wid >> 1;
    const int bm = blockIdx.y * 128;
    const int bn = blockIdx.x * 128;

    const int lrow  = tid >> 1;
    const int lkb   = (tid & 1) << 4;
    const float* Ag = A + (size_t)(bm + lrow) * K + lkb;
    const float* Bg = B + (size_t)(bn + lrow) * K + lkb;

    float acc[4][4][4];
#pragma unroll
    for (int i = 0; i < 4; i++)
#pragma unroll
        for (int j = 0; j < 4; j++)
#pragma unroll
            for (int r = 0; r < 4; r++) acc[i][j][r] = 0.f;

    const int nkt = K >> 5;

    /* prologue: tile 0 -> buf 0 */
    float4 pa[4], pb[4];
#pragma unroll
    for (int i = 0; i < 4; i++) {
        pa[i] = *(const float4*)(Ag + i * 4);
        pb[i] = *(const float4*)(Bg + i * 4);
    }
#pragma unroll
    for (int i = 0; i < 4; i++) {
        unsigned* pA = &AsB[lrow * GPITCH + lkb + i * 4];
        pA[0] = tf32_(pa[i].x); pA[1] = tf32_(pa[i].y);
        pA[2] = tf32_(pa[i].z); pA[3] = tf32_(pa[i].w);
        unsigned* pB = &BsB[lrow * GPITCH + lkb + i * 4];
        pB[0] = tf32_(pb[i].x); pB[1] = tf32_(pb[i].y);
        pB[2] = tf32_(pb[i].z); pB[3] = tf32_(pb[i].w);
    }
    __syncthreads();

    for (int kt = 0; kt < nkt; kt++) {
        const int havenext = (kt + 1 < nkt);
        /* LDG prefetch next tile (latency hidden under mma) */
        if (havenext) {
            const float* Agn = Ag + (kt + 1) * 32;
            const float* Bgn = Bg + (kt + 1) * 32;
#pragma unroll
            for (int i = 0; i < 4; i++) {
                pa[i] = *(const float4*)(Agn + i * 4);
                pb[i] = *(const float4*)(Bgn + i * 4);
            }
        }

        const unsigned* As = AsB + (kt & 1) * GBUF;
        const unsigned* Bs = BsB + (kt & 1) * GBUF;

#pragma unroll
        for (int ks = 0; ks < 4; ks++) {
            const int kc = ks * 8 + (lane & 3);
            unsigned af[4][4], bf[4][2];
#pragma unroll
            for (int mt = 0; mt < 4; mt++) {
                int r = warpM * 64 + mt * 16 + (lane >> 2);
                af[mt][0] = As[r * GPITCH + kc];
                af[mt][1] = As[(r + 8) * GPITCH + kc];
                af[mt][2] = As[r * GPITCH + kc + 4];
                af[mt][3] = As[(r + 8) * GPITCH + kc + 4];
            }
#pragma unroll
            for (int nt = 0; nt < 4; nt++) {
                int r = warpN * 32 + nt * 8 + (lane >> 2);
                bf[nt][0] = Bs[r * GPITCH + kc];
                bf[nt][1] = Bs[r * GPITCH + kc + 4];
            }
#pragma unroll
            for (int mt = 0; mt < 4; mt++)
#pragma unroll
                for (int nt = 0; nt < 4; nt++) {
                    asm volatile(
                        "mma.sync.aligned.m16n8k8.row.col.f32.tf32.tf32.f32 "
                        "{%0,%1,%2,%3}, {%4,%5,%6,%7}, {%8,%9}, {%0,%1,%2,%3};"
                        : "+f"(acc[mt][nt][0]), "+f"(acc[mt][nt][1]),
                          "+f"(acc[mt][nt][2]), "+f"(acc[mt][nt][3])
                        : "r"(af[mt][0]), "r"(af[mt][1]),
                          "r"(af[mt][2]), "r"(af[mt][3]),
                          "r"(bf[nt][0]), "r"(bf[nt][1]));
                }
        }

        /* store next tile into the idle buffer (prev compute done:     */
        /* last iteration's end-of-loop sync guarantees it)             */
        if (havenext) {
            unsigned* Asn = AsB + ((kt + 1) & 1) * GBUF;
            unsigned* Bsn = BsB + ((kt + 1) & 1) * GBUF;
#pragma unroll
            for (int i = 0; i < 4; i++) {
                unsigned* pA = &Asn[lrow * GPITCH + lkb + i * 4];
                pA[0] = tf32_(pa[i].x); pA[1] = tf32_(pa[i].y);
                pA[2] = tf32_(pa[i].z); pA[3] = tf32_(pa[i].w);
                unsigned* pB = &Bsn[lrow * GPITCH + lkb + i * 4];
                pB[0] = tf32_(pb[i].x); pB[1] = tf32_(pb[i].y);
                pB[2] = tf32_(pb[i].z); pB[3] = tf32_(pb[i].w);
            }
        }
        __syncthreads();
    }

#pragma unroll
    for (int mt = 0; mt < 4; mt++) {
        int row0 = bm + warpM * 64 + mt * 16 + (lane >> 2);
#pragma unroll
        for (int nt = 0; nt < 4; nt++) {
            int col = bn + warpN * 32 + nt * 8 + ((lane & 3) << 1);
            float b0 = hasBias ? bias[col] : 0.f;
            float b1 = hasBias ? bias[col + 1] : 0.f;
            float2 v0 = make_float2(acc[mt][nt][0] + b0, acc[mt][nt][1] + b1);
            float2 v1 = make_float2(acc[mt][nt][2] + b0, acc[mt][nt][3] + b1);
            *(float2*)(C + (size_t)row0 * N + col) = v0;
            *(float2*)(C + (size_t)(row0 + 8) * N + col) = v1;
        }
    }
}

/* ------------------------------------------------------------------ */
/* depthwise causal conv (K=4) + SiLU + split + k-norm + gate precomp */
/* ------------------------------------------------------------------ */
__global__ void __launch_bounds__(256)
conv_split_kernel(const float* __restrict__ cw, const float* __restrict__ cb,
                  const float* __restrict__ fm, const float* __restrict__ fb)
{
    const int bs = blockIdx.x;
    const int b = bs >> 10;
    const int s = bs & 1023;

    __shared__ float yc[CONVDIM];
    __shared__ float rn[H_];
    __shared__ float fms[H_];

    const float* hrow = g_h + (size_t)bs * HTOT;

    for (int c = threadIdx.x; c < CONVDIM; c += 256) {
        const float4 w4 = *(const float4*)(cw + c * 4);
        float acc = cb[c];
        if (s >= 3) acc += hrow[-3 * HTOT + c] * w4.x;
        if (s >= 2) acc += hrow[-2 * HTOT + c] * w4.y;
        if (s >= 1) acc += hrow[-1 * HTOT + c] * w4.z;
        acc += hrow[c] * w4.w;
        yc[c] = acc * sigmoidf_(acc);
    }
    __syncthreads();

    const int wid = threadIdx.x >> 5;
    const int lane = threadIdx.x & 31;
    {
        float a = yc[512 + wid * 64 + lane];
        float b2 = yc[512 + wid * 64 + 32 + lane];
        float ss = a * a + b2 * b2;
#pragma unroll
        for (int o = 16; o; o >>= 1) ss += __shfl_xor_sync(0xffffffffu, ss, o);
        if (lane == 0) {
            rn[wid] = rsqrtf(ss + 1e-12f);
            fms[wid] = 2.f * sigmoidf_(fm[wid]);
        }
    }
    __syncthreads();

    for (int c = threadIdx.x; c < CONVDIM; c += 256) {
        float val = yc[c];
        if (c < 512) {
            int hd = c >> 6, dk = c & 63;
            g_q[((size_t)(b * H_ + hd) * S_ + s) * DK_ + dk] = val;
        } else if (c < 1024) {
            int cc = c - 512; int hd = cc >> 6, dk = cc & 63;
            g_k[((size_t)(b * H_ + hd) * S_ + s) * DK_ + dk] = val * rn[hd];
        } else if (c < 2048) {
            int cc = c - 1024; int hd = cc >> 7, dv = cc & 127;
            g_v[((size_t)(b * H_ + hd) * S_ + s) * DV_ + dv] = val;
        } else {
            int cc = c - 2048; int hd = cc >> 6, dk = cc & 63;
            float fv = fms[hd] * (val + fb[hd * DK_ + dk]);
            g_g[((size_t)(b * H_ + hd) * S_ + s) * DK_ + dk] = sigmoidf_(fv);
        }
    }
}

/* ------------------------------------------------------------------ */
/* recurrent scan v3: 128-thread CTAs, 4 k-rows each, 2 CTAs/SM.      */
/* FFMA2 + register-resident W column; S double-buffered in smem.     */
/* ------------------------------------------------------------------ */
__global__ void __launch_bounds__(128, 2)
scan_kernel(const float* __restrict__ W)
{
    __shared__ float Ssm[2][4][DV_];   /* [buf][k-row][col] */

    const int bh = blockIdx.y;
    const int kg = blockIdx.x;        /* 0..15, 4 k-rows each */
    const int h  = bh & 7;
    const int vcol = threadIdx.x;     /* 0..127 */

    /* W column -> registers, packed in u-pairs */
    const float* Wh = W + (size_t)h * DV_ * DV_ + vcol;
    unsigned long long wp[64];
#pragma unroll
    for (int i = 0; i < 64; i++)
        wp[i] = pack2_(Wh[(2 * i) * DV_], Wh[(2 * i + 1) * DV_]);

    for (int i = vcol; i < 2 * 4 * DV_; i += 128)
        ((float*)Ssm)[i] = 0.f;
    __syncthreads();

    float s0 = 0.f, s1 = 0.f, s2 = 0.f, s3 = 0.f;

    const float* vb = g_v + (size_t)bh * S_ * DV_ + vcol;
    const size_t qoffb = (size_t)bh * S_ * DK_ + kg * 4;
    const float* qb = g_q + qoffb;
    const float* kb = g_k + qoffb;
    const float* gb = g_g + qoffb;
    float* yo = g_yp + ((size_t)(kg * BH_ + bh) * S_) * DV_ + vcol;

    float  vtc = vb[0];
    float4 qc = *(const float4*)(qb);
    float4 kc = *(const float4*)(kb);
    float4 gc = *(const float4*)(gb);

    int cur = 0;

    for (int t = 0; t < S_; t++) {
        const int tn = (t + 1 < S_) ? (t + 1) : t;
        float  vtn = vb[tn * DV_];
        float4 qn = *(const float4*)(qb + tn * DK_);
        float4 kn = *(const float4*)(kb + tn * DK_);
        float4 gn = *(const float4*)(gb + tn * DK_);

        const ulonglong2* Sr0 = (const ulonglong2*)&Ssm[cur][0][0];
        const ulonglong2* Sr1 = (const ulonglong2*)&Ssm[cur][1][0];
        const ulonglong2* Sr2 = (const ulonglong2*)&Ssm[cur][2][0];
        const ulonglong2* Sr3 = (const ulonglong2*)&Ssm[cur][3][0];

        unsigned long long a0a = 0ull, a0b = 0ull, a1a = 0ull, a1b = 0ull;
        unsigned long long a2a = 0ull, a2b = 0ull, a3a = 0ull, a3b = 0ull;
#pragma unroll
        for (int i = 0; i < 32; i++) {
            ulonglong2 x0 = Sr0[i];
            ulonglong2 x1 = Sr1[i];
            ulonglong2 x2 = Sr2[i];
            ulonglong2 x3 = Sr3[i];
            a0a = fma2_(x0.x, wp[2 * i], a0a); a0b = fma2_(x0.y, wp[2 * i + 1], a0b);
            a1a = fma2_(x1.x, wp[2 * i], a1a); a1b = fma2_(x1.y, wp[2 * i + 1], a1b);
            a2a = fma2_(x2.x, wp[2 * i], a2a); a2b = fma2_(x2.y, wp[2 * i + 1], a2b);
            a3a = fma2_(x3.x, wp[2 * i], a3a); a3b = fma2_(x3.y, wp[2 * i + 1], a3b);
        }
        float p0 = hsum2_(add2_(a0a, a0b));
        float p1 = hsum2_(add2_(a1a, a1b));
        float p2 = hsum2_(add2_(a2a, a2b));
        float p3 = hsum2_(add2_(a3a, a3b));

        float c0 = tanh_fast_(vtc + p0); s0 = fmaf(gc.x, s0, kc.x * c0);
        float c1 = tanh_fast_(vtc + p1); s1 = fmaf(gc.y, s1, kc.y * c1);
        float c2 = tanh_fast_(vtc + p2); s2 = fmaf(gc.z, s2, kc.z * c2);
        float c3 = tanh_fast_(vtc + p3); s3 = fmaf(gc.w, s3, kc.w * c3);

        float ypv = qc.x * s0 + qc.y * s1 + qc.z * s2 + qc.w * s3;

        int nxt = cur ^ 1;
        Ssm[nxt][0][vcol] = s0;
        Ssm[nxt][1][vcol] = s1;
        Ssm[nxt][2][vcol] = s2;
        Ssm[nxt][3][vcol] = s3;
        yo[t * DV_] = ypv;
        __syncthreads();
        cur = nxt;

        vtc = vtn; qc = qn; kc = kn; gc = gn;
    }
}

/* ------------------------------------------------------------------ */
/* reduce partials + v*D + gate*silu + RMSNorm*g_w                    */
/* ------------------------------------------------------------------ */
__global__ void __launch_bounds__(256)
mix_kernel(const float* __restrict__ Dm, const float* __restrict__ gw)
{
    const int bs = blockIdx.x;
    const int b = bs >> 10;
    const int s = bs & 1023;

    __shared__ float ybuf[GDIM];
    __shared__ float red[8];

    float local = 0.f;
    for (int c = threadIdx.x; c < GDIM; c += 256) {
        int hd = c >> 7, dv = c & 127;
        size_t bh = (size_t)b * H_ + hd;
        float acc = 0.f;
#pragma unroll
        for (int kg = 0; kg < KGROUPS; kg++)
            acc += g_yp[(((size_t)kg * BH_ + bh) * S_ + s) * DV_ + dv];
        float vv = g_v[(bh * S_ + s) * DV_ + dv];
        acc = fmaf(vv, Dm[hd * DV_ + dv], acc);
        float gt = g_h[(size_t)bs * HTOT + CONVDIM + c];
        acc *= gt * sigmoidf_(gt);
        ybuf[c] = acc;
        local = fmaf(acc, acc, local);
    }
#pragma unroll
    for (int o = 16; o; o >>= 1) local += __shfl_xor_sync(0xffffffffu, local, o);
    if ((threadIdx.x & 31) == 0) red[threadIdx.x >> 5] = local;
    __syncthreads();
    if (threadIdx.x == 0) {
        float tot = 0.f;
#pragma unroll
        for (int i = 0; i < 8; i++) tot += red[i];
        red[0] = rsqrtf(tot / (float)GDIM + 1e-6f);
    }
    __syncthreads();
    float rms = red[0];
    for (int c = threadIdx.x; c < GDIM; c += 256)
        g_y2[(size_t)bs * GDIM + c] = ybuf[c] * rms * gw[c];
}

/* ------------------------------------------------------------------ */
extern "C" void kernel_launch(void* const* d_in, const int* in_sizes, int n_in,
                              void* d_out, int out_size)
{
    const float* x    = (const float*)d_in[0];
    const float* w_in = (const float*)d_in[1];
    const float* b_in = (const float*)d_in[2];
    const float* cw   = (const float*)d_in[3];
    const float* cb   = (const float*)d_in[4];
    const float* Dm   = (const float*)d_in[5];
    const float* Wst  = (const float*)d_in[6];
    const float* fm   = (const float*)d_in[7];
    const float* fb   = (const float*)d_in[8];
    const float* gw   = (const float*)d_in[9];
    const float* wout = (const float*)d_in[10];
    float* out = (float*)d_out;

    void *ph = 0, *py2 = 0;
    cudaGetSymbolAddress(&ph, g_h);
    cudaGetSymbolAddress(&py2, g_y2);

    cudaFuncSetAttribute(gemm_tf32, cudaFuncAttributeMaxDynamicSharedMemorySize,
                         GEMM_SMEM);

    /* 1. in-projection (tf32 tensor cores, pipelined) */
    gemm_tf32<<<dim3(HTOT / 128, MTOT / 128), 256, GEMM_SMEM>>>(
        x, w_in, b_in, (float*)ph, MTOT, HTOT, DIN, 1);
    /* 2. conv + silu + split + knorm + gate precompute */
    conv_split_kernel<<<MTOT, 256>>>(cw, cb, fm, fb);
    /* 3. recurrent scan (FFMA2 + register W, 2 CTAs/SM) */
    scan_kernel<<<dim3(KGROUPS, BH_), 128>>>(Wst);
    /* 4. reduce + v*D + gate + RMSNorm */
    mix_kernel<<<MTOT, 256>>>(Dm, gw);
    /* 5. out-projection (tf32 tensor cores, pipelined) */
    gemm_tf32<<<dim3(DOUT / 128, MTOT / 128), 256, GEMM_SMEM>>>(
        (const float*)py2, wout, 0, out, MTOT, DOUT, GDIM, 0);
}

// round 7
// speedup vs baseline: 1.3126x; 1.3126x over previous
#include <cuda_runtime.h>
#include <math.h>

#define B_      2
#define S_      1024
#define DIN     2048
#define DOUT    2048
#define H_      8
#define DK_     64
#define DV_     128
#define CONVDIM 2560
#define GDIM    1024
#define HTOT    3584   /* CONVDIM + GDIM */
#define MTOT    2048   /* B_*S_ */
#define BH_     16     /* B_*H_ */
#define KGROUPS 4      /* DK_/16 : 16 k-rows per scan CTA */

/* ------------------------------------------------------------------ */
__device__ float g_h [MTOT * HTOT];
__device__ float g_q [BH_ * S_ * DK_];
__device__ float g_k [BH_ * S_ * DK_];
__device__ float g_g [BH_ * S_ * DK_];
__device__ float g_v [BH_ * S_ * DV_];
__device__ float g_yp[KGROUPS * BH_ * S_ * DV_];
__device__ float g_y2[MTOT * GDIM];

__device__ __forceinline__ float sigmoidf_(float x) { return 1.f / (1.f + expf(-x)); }

__device__ __forceinline__ unsigned tf32_(float x) {
    unsigned r;
    asm("cvt.rna.tf32.f32 %0, %1;" : "=r"(r) : "f"(x));
    return r;
}
__device__ __forceinline__ float tanh_fast_(float x) {
    float r;
    asm("tanh.approx.f32 %0, %1;" : "=f"(r) : "f"(x));
    return r;
}

/* ------------------------------------------------------------------ */
/* TF32 tensor-core GEMM (NT), 2-stage smem pipeline, 1 sync/k-tile   */
/* ------------------------------------------------------------------ */
#define GPITCH 36
#define GBUF   (128 * GPITCH)
#define GEMM_SMEM (4 * GBUF * 4)

__global__ void __launch_bounds__(256)
gemm_tf32(const float* __restrict__ A, const float* __restrict__ B,
          const float* __restrict__ bias, float* __restrict__ C,
          int M, int N, int K, int hasBias)
{
    extern __shared__ unsigned smemU[];
    unsigned* AsB = smemU;
    unsigned* BsB = smemU + 2 * GBUF;

    const int tid  = threadIdx.x;
    const int lane = tid & 31;
    const int wid  = tid >> 5;
    const int warpM = wid & 1;
    const int warpN = wid >> 1;
    const int bm = blockIdx.y * 128;
    const int bn = blockIdx.x * 128;

    const int lrow  = tid >> 1;
    const int lkb   = (tid & 1) << 4;
    const float* Ag = A + (size_t)(bm + lrow) * K + lkb;
    const float* Bg = B + (size_t)(bn + lrow) * K + lkb;

    float acc[4][4][4];
#pragma unroll
    for (int i = 0; i < 4; i++)
#pragma unroll
        for (int j = 0; j < 4; j++)
#pragma unroll
            for (int r = 0; r < 4; r++) acc[i][j][r] = 0.f;

    const int nkt = K >> 5;

    float4 pa[4], pb[4];
#pragma unroll
    for (int i = 0; i < 4; i++) {
        pa[i] = *(const float4*)(Ag + i * 4);
        pb[i] = *(const float4*)(Bg + i * 4);
    }
#pragma unroll
    for (int i = 0; i < 4; i++) {
        unsigned* pA = &AsB[lrow * GPITCH + lkb + i * 4];
        pA[0] = tf32_(pa[i].x); pA[1] = tf32_(pa[i].y);
        pA[2] = tf32_(pa[i].z); pA[3] = tf32_(pa[i].w);
        unsigned* pB = &BsB[lrow * GPITCH + lkb + i * 4];
        pB[0] = tf32_(pb[i].x); pB[1] = tf32_(pb[i].y);
        pB[2] = tf32_(pb[i].z); pB[3] = tf32_(pb[i].w);
    }
    __syncthreads();

    for (int kt = 0; kt < nkt; kt++) {
        const int havenext = (kt + 1 < nkt);
        if (havenext) {
            const float* Agn = Ag + (kt + 1) * 32;
            const float* Bgn = Bg + (kt + 1) * 32;
#pragma unroll
            for (int i = 0; i < 4; i++) {
                pa[i] = *(const float4*)(Agn + i * 4);
                pb[i] = *(const float4*)(Bgn + i * 4);
            }
        }

        const unsigned* As = AsB + (kt & 1) * GBUF;
        const unsigned* Bs = BsB + (kt & 1) * GBUF;

#pragma unroll
        for (int ks = 0; ks < 4; ks++) {
            const int kc = ks * 8 + (lane & 3);
            unsigned af[4][4], bf[4][2];
#pragma unroll
            for (int mt = 0; mt < 4; mt++) {
                int r = warpM * 64 + mt * 16 + (lane >> 2);
                af[mt][0] = As[r * GPITCH + kc];
                af[mt][1] = As[(r + 8) * GPITCH + kc];
                af[mt][2] = As[r * GPITCH + kc + 4];
                af[mt][3] = As[(r + 8) * GPITCH + kc + 4];
            }
#pragma unroll
            for (int nt = 0; nt < 4; nt++) {
                int r = warpN * 32 + nt * 8 + (lane >> 2);
                bf[nt][0] = Bs[r * GPITCH + kc];
                bf[nt][1] = Bs[r * GPITCH + kc + 4];
            }
#pragma unroll
            for (int mt = 0; mt < 4; mt++)
#pragma unroll
                for (int nt = 0; nt < 4; nt++) {
                    asm volatile(
                        "mma.sync.aligned.m16n8k8.row.col.f32.tf32.tf32.f32 "
                        "{%0,%1,%2,%3}, {%4,%5,%6,%7}, {%8,%9}, {%0,%1,%2,%3};"
                        : "+f"(acc[mt][nt][0]), "+f"(acc[mt][nt][1]),
                          "+f"(acc[mt][nt][2]), "+f"(acc[mt][nt][3])
                        : "r"(af[mt][0]), "r"(af[mt][1]),
                          "r"(af[mt][2]), "r"(af[mt][3]),
                          "r"(bf[nt][0]), "r"(bf[nt][1]));
                }
        }

        if (havenext) {
            unsigned* Asn = AsB + ((kt + 1) & 1) * GBUF;
            unsigned* Bsn = BsB + ((kt + 1) & 1) * GBUF;
#pragma unroll
            for (int i = 0; i < 4; i++) {
                unsigned* pA = &Asn[lrow * GPITCH + lkb + i * 4];
                pA[0] = tf32_(pa[i].x); pA[1] = tf32_(pa[i].y);
                pA[2] = tf32_(pa[i].z); pA[3] = tf32_(pa[i].w);
                unsigned* pB = &Bsn[lrow * GPITCH + lkb + i * 4];
                pB[0] = tf32_(pb[i].x); pB[1] = tf32_(pb[i].y);
                pB[2] = tf32_(pb[i].z); pB[3] = tf32_(pb[i].w);
            }
        }
        __syncthreads();
    }

#pragma unroll
    for (int mt = 0; mt < 4; mt++) {
        int row0 = bm + warpM * 64 + mt * 16 + (lane >> 2);
#pragma unroll
        for (int nt = 0; nt < 4; nt++) {
            int col = bn + warpN * 32 + nt * 8 + ((lane & 3) << 1);
            float b0 = hasBias ? bias[col] : 0.f;
            float b1 = hasBias ? bias[col + 1] : 0.f;
            float2 v0 = make_float2(acc[mt][nt][0] + b0, acc[mt][nt][1] + b1);
            float2 v1 = make_float2(acc[mt][nt][2] + b0, acc[mt][nt][3] + b1);
            *(float2*)(C + (size_t)row0 * N + col) = v0;
            *(float2*)(C + (size_t)(row0 + 8) * N + col) = v1;
        }
    }
}

/* ------------------------------------------------------------------ */
/* depthwise causal conv (K=4) + SiLU + split + k-norm + gate precomp */
/* ------------------------------------------------------------------ */
__global__ void __launch_bounds__(256)
conv_split_kernel(const float* __restrict__ cw, const float* __restrict__ cb,
                  const float* __restrict__ fm, const float* __restrict__ fb)
{
    const int bs = blockIdx.x;
    const int b = bs >> 10;
    const int s = bs & 1023;

    __shared__ float yc[CONVDIM];
    __shared__ float rn[H_];
    __shared__ float fms[H_];

    const float* hrow = g_h + (size_t)bs * HTOT;

    for (int c = threadIdx.x; c < CONVDIM; c += 256) {
        const float4 w4 = *(const float4*)(cw + c * 4);
        float acc = cb[c];
        if (s >= 3) acc += hrow[-3 * HTOT + c] * w4.x;
        if (s >= 2) acc += hrow[-2 * HTOT + c] * w4.y;
        if (s >= 1) acc += hrow[-1 * HTOT + c] * w4.z;
        acc += hrow[c] * w4.w;
        yc[c] = acc * sigmoidf_(acc);
    }
    __syncthreads();

    const int wid = threadIdx.x >> 5;
    const int lane = threadIdx.x & 31;
    {
        float a = yc[512 + wid * 64 + lane];
        float b2 = yc[512 + wid * 64 + 32 + lane];
        float ss = a * a + b2 * b2;
#pragma unroll
        for (int o = 16; o; o >>= 1) ss += __shfl_xor_sync(0xffffffffu, ss, o);
        if (lane == 0) {
            rn[wid] = rsqrtf(ss + 1e-12f);
            fms[wid] = 2.f * sigmoidf_(fm[wid]);
        }
    }
    __syncthreads();

    for (int c = threadIdx.x; c < CONVDIM; c += 256) {
        float val = yc[c];
        if (c < 512) {
            int hd = c >> 6, dk = c & 63;
            g_q[((size_t)(b * H_ + hd) * S_ + s) * DK_ + dk] = val;
        } else if (c < 1024) {
            int cc = c - 512; int hd = cc >> 6, dk = cc & 63;
            g_k[((size_t)(b * H_ + hd) * S_ + s) * DK_ + dk] = val * rn[hd];
        } else if (c < 2048) {
            int cc = c - 1024; int hd = cc >> 7, dv = cc & 127;
            g_v[((size_t)(b * H_ + hd) * S_ + s) * DV_ + dv] = val;
        } else {
            int cc = c - 2048; int hd = cc >> 6, dk = cc & 63;
            float fv = fms[hd] * (val + fb[hd * DK_ + dk]);
            g_g[((size_t)(b * H_ + hd) * S_ + s) * DK_ + dk] = sigmoidf_(fv);
        }
    }
}

/* ------------------------------------------------------------------ */
/* recurrent scan v5: tensor-core, split-W (Whi+Wlo) for fp32-grade   */
/* parameter precision. CTA = (kg, bh): 16 state rows, 256 thr/8 wrp. */
/* Warp w owns cols [w*16, w*16+16): Whi/Wlo as persistent B-frags.   */
/* Exact fp32 S lives in per-thread registers (each thread re-reads   */
/* exactly what it wrote); smem holds only the tf32-truncated copy    */
/* for mma A-fragments, double buffered.                              */
/* ------------------------------------------------------------------ */
#define SPITCH 132

__global__ void __launch_bounds__(256, 1)
scan_kernel(const float* __restrict__ W)
{
    __shared__ float Ssm[2][16][SPITCH];   /* tf32-truncated S        */

    const int bh = blockIdx.y;
    const int kg = blockIdx.x;             /* 0..3 -> rows kg*16..+15 */
    const int h  = bh & 7;
    const int tid  = threadIdx.x;
    const int lane = tid & 31;
    const int wrp  = tid >> 5;             /* 0..7 col-slice index    */
    const int wn   = wrp * 16;

    const int r1 = lane >> 2;              /* 0..7  */
    const int lq = lane & 3;               /* 0..3  */

    /* persistent split-W B-fragments */
    const float* Wh = W + (size_t)h * DV_ * DV_;
    unsigned bhi[16][2][2], blo[16][2][2];
#pragma unroll
    for (int kt = 0; kt < 16; kt++)
#pragma unroll
        for (int nt = 0; nt < 2; nt++) {
            int u0 = kt * 8 + lq;
            int w  = wn + nt * 8 + r1;
            float w0 = Wh[(size_t)u0 * DV_ + w];
            float w1 = Wh[(size_t)(u0 + 4) * DV_ + w];
            unsigned h0 = tf32_(w0), h1 = tf32_(w1);
            bhi[kt][nt][0] = h0;
            bhi[kt][nt][1] = h1;
            blo[kt][nt][0] = tf32_(w0 - __uint_as_float(h0));
            blo[kt][nt][1] = tf32_(w1 - __uint_as_float(h1));
        }

    for (int i = tid; i < 2 * 16 * SPITCH; i += 256)
        ((float*)Ssm)[i] = 0.f;
    __syncthreads();

    /* exact fp32 state in registers: rows (r1, r1+8), cols
       wn + nt*8 + lq*2 (+1)  -> sreg[nt][{r1c0,r1c1,r2c0,r2c1}] */
    float sreg[2][4];
#pragma unroll
    for (int nt = 0; nt < 2; nt++)
#pragma unroll
        for (int i = 0; i < 4; i++) sreg[nt][i] = 0.f;

    const float* qp = g_q + ((size_t)bh * S_) * DK_ + kg * 16;
    const float* kp = g_k + ((size_t)bh * S_) * DK_ + kg * 16;
    const float* gp = g_g + ((size_t)bh * S_) * DK_ + kg * 16;
    const float* vp = g_v + ((size_t)bh * S_) * DV_ + wn + lq * 2;
    float* yo = g_yp + ((size_t)(kg * BH_ + bh) * S_) * DV_ + wn + lq * 2;

    /* prefetch t = 0 */
    float q1 = qp[r1], q2 = qp[r1 + 8];
    float k1 = kp[r1], k2 = kp[r1 + 8];
    float gg1 = gp[r1], gg2 = gp[r1 + 8];
    float2 vc[2];
#pragma unroll
    for (int nt = 0; nt < 2; nt++) vc[nt] = *(const float2*)(vp + nt * 8);

    int cur = 0;

    for (int t = 0; t < S_; t++) {
        const int tn = (t + 1 < S_) ? (t + 1) : t;
        float qn1 = qp[tn * DK_ + r1], qn2 = qp[tn * DK_ + r1 + 8];
        float kn1 = kp[tn * DK_ + r1], kn2 = kp[tn * DK_ + r1 + 8];
        float gn1 = gp[tn * DK_ + r1], gn2 = gp[tn * DK_ + r1 + 8];
        float2 vn[2];
#pragma unroll
        for (int nt = 0; nt < 2; nt++)
            vn[nt] = *(const float2*)(vp + tn * DV_ + nt * 8);

        /* P = v + S@Whi + S@Wlo, accumulators seeded with v */
        float acc[2][4];
#pragma unroll
        for (int nt = 0; nt < 2; nt++) {
            acc[nt][0] = vc[nt].x; acc[nt][1] = vc[nt].y;
            acc[nt][2] = vc[nt].x; acc[nt][3] = vc[nt].y;
        }

        const float(*Sb)[SPITCH] = Ssm[cur];
#pragma unroll
        for (int kt = 0; kt < 16; kt++) {
            int kc = kt * 8 + lq;
            unsigned a0 = __float_as_uint(Sb[r1][kc]);
            unsigned a1 = __float_as_uint(Sb[r1 + 8][kc]);
            unsigned a2 = __float_as_uint(Sb[r1][kc + 4]);
            unsigned a3 = __float_as_uint(Sb[r1 + 8][kc + 4]);
#pragma unroll
            for (int nt = 0; nt < 2; nt++) {
                asm volatile(
                    "mma.sync.aligned.m16n8k8.row.col.f32.tf32.tf32.f32 "
                    "{%0,%1,%2,%3}, {%4,%5,%6,%7}, {%8,%9}, {%0,%1,%2,%3};"
                    : "+f"(acc[nt][0]), "+f"(acc[nt][1]),
                      "+f"(acc[nt][2]), "+f"(acc[nt][3])
                    : "r"(a0), "r"(a1), "r"(a2), "r"(a3),
                      "r"(bhi[kt][nt][0]), "r"(bhi[kt][nt][1]));
                asm volatile(
                    "mma.sync.aligned.m16n8k8.row.col.f32.tf32.tf32.f32 "
                    "{%0,%1,%2,%3}, {%4,%5,%6,%7}, {%8,%9}, {%0,%1,%2,%3};"
                    : "+f"(acc[nt][0]), "+f"(acc[nt][1]),
                      "+f"(acc[nt][2]), "+f"(acc[nt][3])
                    : "r"(a0), "r"(a1), "r"(a2), "r"(a3),
                      "r"(blo[kt][nt][0]), "r"(blo[kt][nt][1]));
            }
        }

        /* state update in exact fp32 registers + truncated store */
        float(*Sn)[SPITCH] = Ssm[cur ^ 1];
        float y0t[2], y1t[2];
#pragma unroll
        for (int nt = 0; nt < 2; nt++) {
            int col = wn + nt * 8 + lq * 2;
            float s00 = fmaf(gg1, sreg[nt][0], k1 * tanh_fast_(acc[nt][0]));
            float s01 = fmaf(gg1, sreg[nt][1], k1 * tanh_fast_(acc[nt][1]));
            float s10 = fmaf(gg2, sreg[nt][2], k2 * tanh_fast_(acc[nt][2]));
            float s11 = fmaf(gg2, sreg[nt][3], k2 * tanh_fast_(acc[nt][3]));
            sreg[nt][0] = s00; sreg[nt][1] = s01;
            sreg[nt][2] = s10; sreg[nt][3] = s11;
            *(float2*)&Sn[r1][col] = make_float2(
                __uint_as_float(tf32_(s00)), __uint_as_float(tf32_(s01)));
            *(float2*)&Sn[r1 + 8][col] = make_float2(
                __uint_as_float(tf32_(s10)), __uint_as_float(tf32_(s11)));
            y0t[nt] = fmaf(q1, s00, q2 * s10);
            y1t[nt] = fmaf(q1, s01, q2 * s11);
        }
        /* reduce over the 8 row-lane groups (same lane&3) */
#pragma unroll
        for (int o = 4; o <= 16; o <<= 1) {
#pragma unroll
            for (int nt = 0; nt < 2; nt++) {
                y0t[nt] += __shfl_xor_sync(0xffffffffu, y0t[nt], o);
                y1t[nt] += __shfl_xor_sync(0xffffffffu, y1t[nt], o);
            }
        }
        if (lane < 4) {
#pragma unroll
            for (int nt = 0; nt < 2; nt++)
                *(float2*)(yo + (size_t)t * DV_ + nt * 8) =
                    make_float2(y0t[nt], y1t[nt]);
        }

        __syncthreads();
        cur ^= 1;
        q1 = qn1; q2 = qn2; k1 = kn1; k2 = kn2; gg1 = gn1; gg2 = gn2;
#pragma unroll
        for (int nt = 0; nt < 2; nt++) vc[nt] = vn[nt];
    }
}

/* ------------------------------------------------------------------ */
/* reduce partials + v*D + gate*silu + RMSNorm*g_w                    */
/* ------------------------------------------------------------------ */
__global__ void __launch_bounds__(256)
mix_kernel(const float* __restrict__ Dm, const float* __restrict__ gw)
{
    const int bs = blockIdx.x;
    const int b = bs >> 10;
    const int s = bs & 1023;

    __shared__ float ybuf[GDIM];
    __shared__ float red[8];

    float local = 0.f;
    for (int c = threadIdx.x; c < GDIM; c += 256) {
        int hd = c >> 7, dv = c & 127;
        size_t bh = (size_t)b * H_ + hd;
        float acc = 0.f;
#pragma unroll
        for (int kg = 0; kg < KGROUPS; kg++)
            acc += g_yp[(((size_t)kg * BH_ + bh) * S_ + s) * DV_ + dv];
        float vv = g_v[(bh * S_ + s) * DV_ + dv];
        acc = fmaf(vv, Dm[hd * DV_ + dv], acc);
        float gt = g_h[(size_t)bs * HTOT + CONVDIM + c];
        acc *= gt * sigmoidf_(gt);
        ybuf[c] = acc;
        local = fmaf(acc, acc, local);
    }
#pragma unroll
    for (int o = 16; o; o >>= 1) local += __shfl_xor_sync(0xffffffffu, local, o);
    if ((threadIdx.x & 31) == 0) red[threadIdx.x >> 5] = local;
    __syncthreads();
    if (threadIdx.x == 0) {
        float tot = 0.f;
#pragma unroll
        for (int i = 0; i < 8; i++) tot += red[i];
        red[0] = rsqrtf(tot / (float)GDIM + 1e-6f);
    }
    __syncthreads();
    float rms = red[0];
    for (int c = threadIdx.x; c < GDIM; c += 256)
        g_y2[(size_t)bs * GDIM + c] = ybuf[c] * rms * gw[c];
}

/* ------------------------------------------------------------------ */
extern "C" void kernel_launch(void* const* d_in, const int* in_sizes, int n_in,
                              void* d_out, int out_size)
{
    const float* x    = (const float*)d_in[0];
    const float* w_in = (const float*)d_in[1];
    const float* b_in = (const float*)d_in[2];
    const float* cw   = (const float*)d_in[3];
    const float* cb   = (const float*)d_in[4];
    const float* Dm   = (const float*)d_in[5];
    const float* Wst  = (const float*)d_in[6];
    const float* fm   = (const float*)d_in[7];
    const float* fb   = (const float*)d_in[8];
    const float* gw   = (const float*)d_in[9];
    const float* wout = (const float*)d_in[10];
    float* out = (float*)d_out;

    void *ph = 0, *py2 = 0;
    cudaGetSymbolAddress(&ph, g_h);
    cudaGetSymbolAddress(&py2, g_y2);

    cudaFuncSetAttribute(gemm_tf32, cudaFuncAttributeMaxDynamicSharedMemorySize,
                         GEMM_SMEM);

    /* 1. in-projection (tf32 tensor cores, pipelined) */
    gemm_tf32<<<dim3(HTOT / 128, MTOT / 128), 256, GEMM_SMEM>>>(
        x, w_in, b_in, (float*)ph, MTOT, HTOT, DIN, 1);
    /* 2. conv + silu + split + knorm + gate precompute */
    conv_split_kernel<<<MTOT, 256>>>(cw, cb, fm, fb);
    /* 3. recurrent scan (tensor-core, split-W) */
    scan_kernel<<<dim3(KGROUPS, BH_), 256>>>(Wst);
    /* 4. reduce + v*D + gate + RMSNorm */
    mix_kernel<<<MTOT, 256>>>(Dm, gw);
    /* 5. out-projection (tf32 tensor cores, pipelined) */
    gemm_tf32<<<dim3(DOUT / 128, MTOT / 128), 256, GEMM_SMEM>>>(
        (const float*)py2, wout, 0, out, MTOT, DOUT, GDIM, 0);
}

// round 12
// speedup vs baseline: 1.3251x; 1.0096x over previous
#include <cuda_runtime.h>
#include <math.h>

#define B_      2
#define S_      1024
#define DIN     2048
#define DOUT    2048
#define H_      8
#define DK_     64
#define DV_     128
#define CONVDIM 2560
#define GDIM    1024
#define HTOT    3584   /* CONVDIM + GDIM */
#define MTOT    2048   /* B_*S_ */
#define BH_     16     /* B_*H_ */
#define KGROUPS 4      /* DK_/16 : 16 k-rows per scan CTA */

/* ------------------------------------------------------------------ */
__device__ float g_h [MTOT * HTOT];
__device__ float g_q [BH_ * S_ * DK_];
__device__ float g_k [BH_ * S_ * DK_];
__device__ float g_g [BH_ * S_ * DK_];
__device__ float g_v [BH_ * S_ * DV_];
__device__ float g_yp[KGROUPS * BH_ * S_ * DV_];
__device__ float g_y2[MTOT * GDIM];

__device__ __forceinline__ float sigmoidf_(float x) { return 1.f / (1.f + expf(-x)); }

__device__ __forceinline__ unsigned tf32_(float x) {
    unsigned r;
    asm("cvt.rna.tf32.f32 %0, %1;" : "=r"(r) : "f"(x));
    return r;
}
__device__ __forceinline__ float tanh_fast_(float x) {
    float r;
    asm("tanh.approx.f32 %0, %1;" : "=f"(r) : "f"(x));
    return r;
}

/* ------------------------------------------------------------------ */
/* TF32 tensor-core GEMM (NT): C[M,N] = A[M,K]*B[N,K]^T (+bias)       */
/* 128x128 CTA tile, BK=32, 512 threads = 16 warps (4M x 4N),         */
/* 32x32 warp tile -> ~90 regs/thread -> 4 warps/SMSP occupancy.      */
/* ------------------------------------------------------------------ */
#define GPITCH 36

__global__ void __launch_bounds__(512)
gemm_tf32(const float* __restrict__ A, const float* __restrict__ B,
          const float* __restrict__ bias, float* __restrict__ C,
          int M, int N, int K, int hasBias)
{
    __shared__ unsigned As[128 * GPITCH];
    __shared__ unsigned Bs[128 * GPITCH];

    const int tid  = threadIdx.x;
    const int lane = tid & 31;
    const int wid  = tid >> 5;
    const int warpM = wid & 3;        /* 0..3 */
    const int warpN = wid >> 2;       /* 0..3 */
    const int bm = blockIdx.y * 128;
    const int bn = blockIdx.x * 128;

    /* loader: row = tid>>2 (0..127), colbase = (tid&3)*8 */
    const int lrow = tid >> 2;
    const int lcb  = (tid & 3) << 3;
    const float* Ag = A + (size_t)(bm + lrow) * K + lcb;
    const float* Bg = B + (size_t)(bn + lrow) * K + lcb;

    float acc[2][4][4];
#pragma unroll
    for (int i = 0; i < 2; i++)
#pragma unroll
        for (int j = 0; j < 4; j++)
#pragma unroll
            for (int r = 0; r < 4; r++) acc[i][j][r] = 0.f;

    const int nkt = K >> 5;

    /* prologue: load tile 0 into registers */
    float4 pa[2], pb[2];
#pragma unroll
    for (int i = 0; i < 2; i++) {
        pa[i] = *(const float4*)(Ag + i * 4);
        pb[i] = *(const float4*)(Bg + i * 4);
    }

    for (int kt = 0; kt < nkt; kt++) {
        /* stage to smem (tf32-converted) */
        {
            unsigned* pA = &As[lrow * GPITCH + lcb];
            pA[0] = tf32_(pa[0].x); pA[1] = tf32_(pa[0].y);
            pA[2] = tf32_(pa[0].z); pA[3] = tf32_(pa[0].w);
            pA[4] = tf32_(pa[1].x); pA[5] = tf32_(pa[1].y);
            pA[6] = tf32_(pa[1].z); pA[7] = tf32_(pa[1].w);
            unsigned* pB = &Bs[lrow * GPITCH + lcb];
            pB[0] = tf32_(pb[0].x); pB[1] = tf32_(pb[0].y);
            pB[2] = tf32_(pb[0].z); pB[3] = tf32_(pb[0].w);
            pB[4] = tf32_(pb[1].x); pB[5] = tf32_(pb[1].y);
            pB[6] = tf32_(pb[1].z); pB[7] = tf32_(pb[1].w);
        }
        __syncthreads();

        /* prefetch next tile into registers */
        if (kt + 1 < nkt) {
            const float* Agn = Ag + (kt + 1) * 32;
            const float* Bgn = Bg + (kt + 1) * 32;
#pragma unroll
            for (int i = 0; i < 2; i++) {
                pa[i] = *(const float4*)(Agn + i * 4);
                pb[i] = *(const float4*)(Bgn + i * 4);
            }
        }

        /* compute: 4 k-steps of 8 */
#pragma unroll
        for (int ks = 0; ks < 4; ks++) {
            const int kc = ks * 8 + (lane & 3);
            unsigned af[2][4], bf[4][2];
#pragma unroll
            for (int mt = 0; mt < 2; mt++) {
                int r = warpM * 32 + mt * 16 + (lane >> 2);
                af[mt][0] = As[r * GPITCH + kc];
                af[mt][1] = As[(r + 8) * GPITCH + kc];
                af[mt][2] = As[r * GPITCH + kc + 4];
                af[mt][3] = As[(r + 8) * GPITCH + kc + 4];
            }
#pragma unroll
            for (int nt = 0; nt < 4; nt++) {
                int r = warpN * 32 + nt * 8 + (lane >> 2);
                bf[nt][0] = Bs[r * GPITCH + kc];
                bf[nt][1] = Bs[r * GPITCH + kc + 4];
            }
#pragma unroll
            for (int mt = 0; mt < 2; mt++)
#pragma unroll
                for (int nt = 0; nt < 4; nt++) {
                    asm volatile(
                        "mma.sync.aligned.m16n8k8.row.col.f32.tf32.tf32.f32 "
                        "{%0,%1,%2,%3}, {%4,%5,%6,%7}, {%8,%9}, {%0,%1,%2,%3};"
                        : "+f"(acc[mt][nt][0]), "+f"(acc[mt][nt][1]),
                          "+f"(acc[mt][nt][2]), "+f"(acc[mt][nt][3])
                        : "r"(af[mt][0]), "r"(af[mt][1]),
                          "r"(af[mt][2]), "r"(af[mt][3]),
                          "r"(bf[nt][0]), "r"(bf[nt][1]));
                }
        }
        __syncthreads();
    }

    /* epilogue */
#pragma unroll
    for (int mt = 0; mt < 2; mt++) {
        int row0 = bm + warpM * 32 + mt * 16 + (lane >> 2);
#pragma unroll
        for (int nt = 0; nt < 4; nt++) {
            int col = bn + warpN * 32 + nt * 8 + ((lane & 3) << 1);
            float b0 = hasBias ? bias[col] : 0.f;
            float b1 = hasBias ? bias[col + 1] : 0.f;
            float2 v0 = make_float2(acc[mt][nt][0] + b0, acc[mt][nt][1] + b1);
            float2 v1 = make_float2(acc[mt][nt][2] + b0, acc[mt][nt][3] + b1);
            *(float2*)(C + (size_t)row0 * N + col) = v0;
            *(float2*)(C + (size_t)(row0 + 8) * N + col) = v1;
        }
    }
}

/* ------------------------------------------------------------------ */
/* depthwise causal conv (K=4) + SiLU + split + k-norm + gate precomp */
/* ------------------------------------------------------------------ */
__global__ void __launch_bounds__(256)
conv_split_kernel(const float* __restrict__ cw, const float* __restrict__ cb,
                  const float* __restrict__ fm, const float* __restrict__ fb)
{
    const int bs = blockIdx.x;
    const int b = bs >> 10;
    const int s = bs & 1023;

    __shared__ float yc[CONVDIM];
    __shared__ float rn[H_];
    __shared__ float fms[H_];

    const float* hrow = g_h + (size_t)bs * HTOT;

    for (int c = threadIdx.x; c < CONVDIM; c += 256) {
        const float4 w4 = *(const float4*)(cw + c * 4);
        float acc = cb[c];
        if (s >= 3) acc += hrow[-3 * HTOT + c] * w4.x;
        if (s >= 2) acc += hrow[-2 * HTOT + c] * w4.y;
        if (s >= 1) acc += hrow[-1 * HTOT + c] * w4.z;
        acc += hrow[c] * w4.w;
        yc[c] = acc * sigmoidf_(acc);
    }
    __syncthreads();

    const int wid = threadIdx.x >> 5;
    const int lane = threadIdx.x & 31;
    {
        float a = yc[512 + wid * 64 + lane];
        float b2 = yc[512 + wid * 64 + 32 + lane];
        float ss = a * a + b2 * b2;
#pragma unroll
        for (int o = 16; o; o >>= 1) ss += __shfl_xor_sync(0xffffffffu, ss, o);
        if (lane == 0) {
            rn[wid] = rsqrtf(ss + 1e-12f);
            fms[wid] = 2.f * sigmoidf_(fm[wid]);
        }
    }
    __syncthreads();

    for (int c = threadIdx.x; c < CONVDIM; c += 256) {
        float val = yc[c];
        if (c < 512) {
            int hd = c >> 6, dk = c & 63;
            g_q[((size_t)(b * H_ + hd) * S_ + s) * DK_ + dk] = val;
        } else if (c < 1024) {
            int cc = c - 512; int hd = cc >> 6, dk = cc & 63;
            g_k[((size_t)(b * H_ + hd) * S_ + s) * DK_ + dk] = val * rn[hd];
        } else if (c < 2048) {
            int cc = c - 1024; int hd = cc >> 7, dv = cc & 127;
            g_v[((size_t)(b * H_ + hd) * S_ + s) * DV_ + dv] = val;
        } else {
            int cc = c - 2048; int hd = cc >> 6, dk = cc & 63;
            float fv = fms[hd] * (val + fb[hd * DK_ + dk]);
            g_g[((size_t)(b * H_ + hd) * S_ + s) * DK_ + dk] = sigmoidf_(fv);
        }
    }
}

/* ------------------------------------------------------------------ */
/* recurrent scan v5 (unchanged, passing): tensor-core split-W        */
/* ------------------------------------------------------------------ */
#define SPITCH 132

__global__ void __launch_bounds__(256, 1)
scan_kernel(const float* __restrict__ W)
{
    __shared__ float Ssm[2][16][SPITCH];

    const int bh = blockIdx.y;
    const int kg = blockIdx.x;
    const int h  = bh & 7;
    const int tid  = threadIdx.x;
    const int lane = tid & 31;
    const int wrp  = tid >> 5;
    const int wn   = wrp * 16;

    const int r1 = lane >> 2;
    const int lq = lane & 3;

    const float* Wh = W + (size_t)h * DV_ * DV_;
    unsigned bhi[16][2][2], blo[16][2][2];
#pragma unroll
    for (int kt = 0; kt < 16; kt++) {
#pragma unroll
        for (int nt = 0; nt < 2; nt++) {
            int u0 = kt * 8 + lq;
            int w  = wn + nt * 8 + r1;
            float w0 = Wh[(size_t)u0 * DV_ + w];
            float w1 = Wh[(size_t)(u0 + 4) * DV_ + w];
            unsigned h0 = tf32_(w0), h1 = tf32_(w1);
            bhi[kt][nt][0] = h0;
            bhi[kt][nt][1] = h1;
            blo[kt][nt][0] = tf32_(w0 - __uint_as_float(h0));
            blo[kt][nt][1] = tf32_(w1 - __uint_as_float(h1));
        }
    }

    for (int i = tid; i < 2 * 16 * SPITCH; i += 256)
        ((float*)Ssm)[i] = 0.f;
    __syncthreads();

    float sreg[2][4];
#pragma unroll
    for (int nt = 0; nt < 2; nt++) {
#pragma unroll
        for (int i = 0; i < 4; i++) sreg[nt][i] = 0.f;
    }

    const float* qp = g_q + ((size_t)bh * S_) * DK_ + kg * 16;
    const float* kp = g_k + ((size_t)bh * S_) * DK_ + kg * 16;
    const float* gp = g_g + ((size_t)bh * S_) * DK_ + kg * 16;
    const float* vp = g_v + ((size_t)bh * S_) * DV_ + wn + lq * 2;
    float* yo = g_yp + ((size_t)(kg * BH_ + bh) * S_) * DV_ + wn + lq * 2;

    float q1 = qp[r1], q2 = qp[r1 + 8];
    float k1 = kp[r1], k2 = kp[r1 + 8];
    float gg1 = gp[r1], gg2 = gp[r1 + 8];
    float2 vc[2];
#pragma unroll
    for (int nt = 0; nt < 2; nt++) vc[nt] = *(const float2*)(vp + nt * 8);

    int cur = 0;

    for (int t = 0; t < S_; t++) {
        const int tn = (t + 1 < S_) ? (t + 1) : t;
        float qn1 = qp[tn * DK_ + r1], qn2 = qp[tn * DK_ + r1 + 8];
        float kn1 = kp[tn * DK_ + r1], kn2 = kp[tn * DK_ + r1 + 8];
        float gn1 = gp[tn * DK_ + r1], gn2 = gp[tn * DK_ + r1 + 8];
        float2 vn[2];
#pragma unroll
        for (int nt = 0; nt < 2; nt++)
            vn[nt] = *(const float2*)(vp + tn * DV_ + nt * 8);

        float acc[2][4];
#pragma unroll
        for (int nt = 0; nt < 2; nt++) {
            acc[nt][0] = vc[nt].x; acc[nt][1] = vc[nt].y;
            acc[nt][2] = vc[nt].x; acc[nt][3] = vc[nt].y;
        }

        const float(*Sb)[SPITCH] = Ssm[cur];
#pragma unroll
        for (int kt = 0; kt < 16; kt++) {
            int kc = kt * 8 + lq;
            unsigned a0 = __float_as_uint(Sb[r1][kc]);
            unsigned a1 = __float_as_uint(Sb[r1 + 8][kc]);
            unsigned a2 = __float_as_uint(Sb[r1][kc + 4]);
            unsigned a3 = __float_as_uint(Sb[r1 + 8][kc + 4]);
#pragma unroll
            for (int nt = 0; nt < 2; nt++) {
                asm volatile(
                    "mma.sync.aligned.m16n8k8.row.col.f32.tf32.tf32.f32 "
                    "{%0,%1,%2,%3}, {%4,%5,%6,%7}, {%8,%9}, {%0,%1,%2,%3};"
                    : "+f"(acc[nt][0]), "+f"(acc[nt][1]),
                      "+f"(acc[nt][2]), "+f"(acc[nt][3])
                    : "r"(a0), "r"(a1), "r"(a2), "r"(a3),
                      "r"(bhi[kt][nt][0]), "r"(bhi[kt][nt][1]));
                asm volatile(
                    "mma.sync.aligned.m16n8k8.row.col.f32.tf32.tf32.f32 "
                    "{%0,%1,%2,%3}, {%4,%5,%6,%7}, {%8,%9}, {%0,%1,%2,%3};"
                    : "+f"(acc[nt][0]), "+f"(acc[nt][1]),
                      "+f"(acc[nt][2]), "+f"(acc[nt][3])
                    : "r"(a0), "r"(a1), "r"(a2), "r"(a3),
                      "r"(blo[kt][nt][0]), "r"(blo[kt][nt][1]));
            }
        }

        float(*Sn)[SPITCH] = Ssm[cur ^ 1];
        float y0t[2], y1t[2];
#pragma unroll
        for (int nt = 0; nt < 2; nt++) {
            int col = wn + nt * 8 + lq * 2;
            float s00 = fmaf(gg1, sreg[nt][0], k1 * tanh_fast_(acc[nt][0]));
            float s01 = fmaf(gg1, sreg[nt][1], k1 * tanh_fast_(acc[nt][1]));
            float s10 = fmaf(gg2, sreg[nt][2], k2 * tanh_fast_(acc[nt][2]));
            float s11 = fmaf(gg2, sreg[nt][3], k2 * tanh_fast_(acc[nt][3]));
            sreg[nt][0] = s00; sreg[nt][1] = s01;
            sreg[nt][2] = s10; sreg[nt][3] = s11;
            *(float2*)&Sn[r1][col] = make_float2(
                __uint_as_float(tf32_(s00)), __uint_as_float(tf32_(s01)));
            *(float2*)&Sn[r1 + 8][col] = make_float2(
                __uint_as_float(tf32_(s10)), __uint_as_float(tf32_(s11)));
            y0t[nt] = fmaf(q1, s00, q2 * s10);
            y1t[nt] = fmaf(q1, s01, q2 * s11);
        }
#pragma unroll
        for (int o = 4; o <= 16; o <<= 1) {
#pragma unroll
            for (int nt = 0; nt < 2; nt++) {
                y0t[nt] += __shfl_xor_sync(0xffffffffu, y0t[nt], o);
                y1t[nt] += __shfl_xor_sync(0xffffffffu, y1t[nt], o);
            }
        }
        if (lane < 4) {
#pragma unroll
            for (int nt = 0; nt < 2; nt++)
                *(float2*)(yo + (size_t)t * DV_ + nt * 8) =
                    make_float2(y0t[nt], y1t[nt]);
        }

        __syncthreads();
        cur ^= 1;
        q1 = qn1; q2 = qn2; k1 = kn1; k2 = kn2; gg1 = gn1; gg2 = gn2;
#pragma unroll
        for (int nt = 0; nt < 2; nt++) vc[nt] = vn[nt];
    }
}

/* ------------------------------------------------------------------ */
/* reduce partials + v*D + gate*silu + RMSNorm*g_w                    */
/* ------------------------------------------------------------------ */
__global__ void __launch_bounds__(256)
mix_kernel(const float* __restrict__ Dm, const float* __restrict__ gw)
{
    const int bs = blockIdx.x;
    const int b = bs >> 10;
    const int s = bs & 1023;

    __shared__ float ybuf[GDIM];
    __shared__ float red[8];

    float local = 0.f;
    for (int c = threadIdx.x; c < GDIM; c += 256) {
        int hd = c >> 7, dv = c & 127;
        size_t bh = (size_t)b * H_ + hd;
        float acc = 0.f;
#pragma unroll
        for (int kg = 0; kg < KGROUPS; kg++)
            acc += g_yp[(((size_t)kg * BH_ + bh) * S_ + s) * DV_ + dv];
        float vv = g_v[(bh * S_ + s) * DV_ + dv];
        acc = fmaf(vv, Dm[hd * DV_ + dv], acc);
        float gt = g_h[(size_t)bs * HTOT + CONVDIM + c];
        acc *= gt * sigmoidf_(gt);
        ybuf[c] = acc;
        local = fmaf(acc, acc, local);
    }
#pragma unroll
    for (int o = 16; o; o >>= 1) local += __shfl_xor_sync(0xffffffffu, local, o);
    if ((threadIdx.x & 31) == 0) red[threadIdx.x >> 5] = local;
    __syncthreads();
    if (threadIdx.x == 0) {
        float tot = 0.f;
#pragma unroll
        for (int i = 0; i < 8; i++) tot += red[i];
        red[0] = rsqrtf(tot / (float)GDIM + 1e-6f);
    }
    __syncthreads();
    float rms = red[0];
    for (int c = threadIdx.x; c < GDIM; c += 256)
        g_y2[(size_t)bs * GDIM + c] = ybuf[c] * rms * gw[c];
}

/* ------------------------------------------------------------------ */
extern "C" void kernel_launch(void* const* d_in, const int* in_sizes, int n_in,
                              void* d_out, int out_size)
{
    const float* x    = (const float*)d_in[0];
    const float* w_in = (const float*)d_in[1];
    const float* b_in = (const float*)d_in[2];
    const float* cw   = (const float*)d_in[3];
    const float* cb   = (const float*)d_in[4];
    const float* Dm   = (const float*)d_in[5];
    const float* Wst  = (const float*)d_in[6];
    const float* fm   = (const float*)d_in[7];
    const float* fb   = (const float*)d_in[8];
    const float* gw   = (const float*)d_in[9];
    const float* wout = (const float*)d_in[10];
    float* out = (float*)d_out;

    void *ph = 0, *py2 = 0;
    cudaGetSymbolAddress(&ph, g_h);
    cudaGetSymbolAddress(&py2, g_y2);

    /* 1. in-projection (tf32 mma.sync, 512-thread high-occupancy) */
    gemm_tf32<<<dim3(HTOT / 128, MTOT / 128), 512>>>(
        x, w_in, b_in, (float*)ph, MTOT, HTOT, DIN, 1);
    /* 2. conv + silu + split + knorm + gate precompute */
    conv_split_kernel<<<MTOT, 256>>>(cw, cb, fm, fb);
    /* 3. recurrent scan (tensor-core, split-W) */
    scan_kernel<<<dim3(KGROUPS, BH_), 256>>>(Wst);
    /* 4. reduce + v*D + gate + RMSNorm */
    mix_kernel<<<MTOT, 256>>>(Dm, gw);
    /* 5. out-projection (tf32 mma.sync, 512-thread high-occupancy) */
    gemm_tf32<<<dim3(DOUT / 128, MTOT / 128), 512>>>(
        (const float*)py2, wout, 0, out, MTOT, DOUT, GDIM, 0);
}

// round 13
// speedup vs baseline: 1.4222x; 1.0733x over previous
#include <cuda_runtime.h>
#include <math.h>

#define B_      2
#define S_      1024
#define DIN     2048
#define DOUT    2048
#define H_      8
#define DK_     64
#define DV_     128
#define CONVDIM 2560
#define GDIM    1024
#define HTOT    3584   /* CONVDIM + GDIM */
#define MTOT    2048   /* B_*S_ */
#define BH_     16     /* B_*H_ */
#define KGROUPS 4      /* DK_/16 : 16 k-rows per scan CTA */

/* ------------------------------------------------------------------ */
__device__ float g_h [MTOT * HTOT];
__device__ float g_q [BH_ * S_ * DK_];
__device__ float g_k [BH_ * S_ * DK_];
__device__ float g_g [BH_ * S_ * DK_];
__device__ float g_v [BH_ * S_ * DV_];
__device__ float g_yp[KGROUPS * BH_ * S_ * DV_];
__device__ float g_y2[MTOT * GDIM];

/* tf32-pre-rounded fp32 copies of GEMM operands */
__device__ float g_xr [MTOT * DIN];
__device__ float g_wr [HTOT * DIN];
__device__ float g_wor[DOUT * GDIM];

__device__ __forceinline__ float sigmoidf_(float x) { return 1.f / (1.f + expf(-x)); }

__device__ __forceinline__ unsigned tf32_(float x) {
    unsigned r;
    asm("cvt.rna.tf32.f32 %0, %1;" : "=r"(r) : "f"(x));
    return r;
}
__device__ __forceinline__ float tanh_fast_(float x) {
    float r;
    asm("tanh.approx.f32 %0, %1;" : "=f"(r) : "f"(x));
    return r;
}
__device__ __forceinline__ unsigned smem_u32_(const void* p) {
    unsigned a;
    asm("{ .reg .u64 t; cvta.to.shared.u64 t, %1; cvt.u32.u64 %0, t; }"
        : "=r"(a) : "l"(p));
    return a;
}
__device__ __forceinline__ void cpa16_(unsigned s, const void* g) {
    asm volatile("cp.async.ca.shared.global [%0], [%1], 16;"
                 :: "r"(s), "l"(g) : "memory");
}
#define CPA_COMMIT() asm volatile("cp.async.commit_group;" ::: "memory")

/* ------------------------------------------------------------------ */
/* elementwise tf32 rounding pre-pass                                 */
/* ------------------------------------------------------------------ */
__global__ void __launch_bounds__(256)
round_tf32_kernel(const float* __restrict__ in, float* __restrict__ out, int n)
{
    int i = (blockIdx.x * 256 + threadIdx.x) * 4;
    if (i >= n) return;
    float4 f = *(const float4*)(in + i);
    f.x = __uint_as_float(tf32_(f.x));
    f.y = __uint_as_float(tf32_(f.y));
    f.z = __uint_as_float(tf32_(f.z));
    f.w = __uint_as_float(tf32_(f.w));
    *(float4*)(out + i) = f;
}

/* ------------------------------------------------------------------ */
/* TF32 tensor-core GEMM (NT), inputs pre-rounded to tf32.            */
/* 128x128 CTA tile, BK=32, 512 thr, cp.async 2-stage ring,           */
/* 2 CTAs/SM (8 warps/SMSP).                                          */
/* ------------------------------------------------------------------ */
#define GPITCH 36
#define GBUF   (128 * GPITCH)                  /* floats per stage    */
#define GEMM_SMEM (4 * GBUF * 4)               /* 73728 bytes         */

__global__ void __launch_bounds__(512, 2)
gemm_tf32(const float* __restrict__ A, const float* __restrict__ B,
          const float* __restrict__ bias, float* __restrict__ C,
          int M, int N, int K, int hasBias)
{
    extern __shared__ float smemF[];
    float* AsB = smemF;             /* 2 stages */
    float* BsB = smemF + 2 * GBUF;  /* 2 stages */

    const int tid  = threadIdx.x;
    const int lane = tid & 31;
    const int wid  = tid >> 5;
    const int warpM = wid & 3;
    const int warpN = wid >> 2;
    const int bm = blockIdx.y * 128;
    const int bn = blockIdx.x * 128;

    /* loader: row = tid>>2 (0..127), colbase = (tid&3)*8 */
    const int lrow = tid >> 2;
    const int lcb  = (tid & 3) << 3;
    const float* Ag = A + (size_t)(bm + lrow) * K + lcb;
    const float* Bg = B + (size_t)(bn + lrow) * K + lcb;
    const unsigned sA = smem_u32_(AsB) + (unsigned)(lrow * GPITCH + lcb) * 4u;
    const unsigned sB = smem_u32_(BsB) + (unsigned)(lrow * GPITCH + lcb) * 4u;
    const unsigned stageB = GBUF * 4u;

    float acc[2][4][4];
#pragma unroll
    for (int i = 0; i < 2; i++)
#pragma unroll
        for (int j = 0; j < 4; j++)
#pragma unroll
            for (int r = 0; r < 4; r++) acc[i][j][r] = 0.f;

    const int nkt = K >> 5;

    /* prologue: stage 0 */
    cpa16_(sA, Ag);        cpa16_(sA + 16, Ag + 4);
    cpa16_(sB, Bg);        cpa16_(sB + 16, Bg + 4);
    CPA_COMMIT();

    for (int kt = 0; kt < nkt; kt++) {
        if (kt + 1 < nkt) {
            const unsigned off = ((kt + 1) & 1) * stageB;
            const float* Agn = Ag + (kt + 1) * 32;
            const float* Bgn = Bg + (kt + 1) * 32;
            cpa16_(sA + off, Agn);       cpa16_(sA + off + 16, Agn + 4);
            cpa16_(sB + off, Bgn);       cpa16_(sB + off + 16, Bgn + 4);
            CPA_COMMIT();
            asm volatile("cp.async.wait_group 1;" ::: "memory");
        } else {
            asm volatile("cp.async.wait_group 0;" ::: "memory");
        }
        __syncthreads();

        const float* As = AsB + (kt & 1) * GBUF;
        const float* Bs = BsB + (kt & 1) * GBUF;

#pragma unroll
        for (int ks = 0; ks < 4; ks++) {
            const int kc = ks * 8 + (lane & 3);
            unsigned af[2][4], bf[4][2];
#pragma unroll
            for (int mt = 0; mt < 2; mt++) {
                int r = warpM * 32 + mt * 16 + (lane >> 2);
                af[mt][0] = __float_as_uint(As[r * GPITCH + kc]);
                af[mt][1] = __float_as_uint(As[(r + 8) * GPITCH + kc]);
                af[mt][2] = __float_as_uint(As[r * GPITCH + kc + 4]);
                af[mt][3] = __float_as_uint(As[(r + 8) * GPITCH + kc + 4]);
            }
#pragma unroll
            for (int nt = 0; nt < 4; nt++) {
                int r = warpN * 32 + nt * 8 + (lane >> 2);
                bf[nt][0] = __float_as_uint(Bs[r * GPITCH + kc]);
                bf[nt][1] = __float_as_uint(Bs[r * GPITCH + kc + 4]);
            }
#pragma unroll
            for (int mt = 0; mt < 2; mt++)
#pragma unroll
                for (int nt = 0; nt < 4; nt++) {
                    asm volatile(
                        "mma.sync.aligned.m16n8k8.row.col.f32.tf32.tf32.f32 "
                        "{%0,%1,%2,%3}, {%4,%5,%6,%7}, {%8,%9}, {%0,%1,%2,%3};"
                        : "+f"(acc[mt][nt][0]), "+f"(acc[mt][nt][1]),
                          "+f"(acc[mt][nt][2]), "+f"(acc[mt][nt][3])
                        : "r"(af[mt][0]), "r"(af[mt][1]),
                          "r"(af[mt][2]), "r"(af[mt][3]),
                          "r"(bf[nt][0]), "r"(bf[nt][1]));
                }
        }
        __syncthreads();
    }

    /* epilogue */
#pragma unroll
    for (int mt = 0; mt < 2; mt++) {
        int row0 = bm + warpM * 32 + mt * 16 + (lane >> 2);
#pragma unroll
        for (int nt = 0; nt < 4; nt++) {
            int col = bn + warpN * 32 + nt * 8 + ((lane & 3) << 1);
            float b0 = hasBias ? bias[col] : 0.f;
            float b1 = hasBias ? bias[col + 1] : 0.f;
            float2 v0 = make_float2(acc[mt][nt][0] + b0, acc[mt][nt][1] + b1);
            float2 v1 = make_float2(acc[mt][nt][2] + b0, acc[mt][nt][3] + b1);
            *(float2*)(C + (size_t)row0 * N + col) = v0;
            *(float2*)(C + (size_t)(row0 + 8) * N + col) = v1;
        }
    }
}

/* ------------------------------------------------------------------ */
/* depthwise causal conv (K=4) + SiLU + split + k-norm + gate precomp */
/* ------------------------------------------------------------------ */
__global__ void __launch_bounds__(256)
conv_split_kernel(const float* __restrict__ cw, const float* __restrict__ cb,
                  const float* __restrict__ fm, const float* __restrict__ fb)
{
    const int bs = blockIdx.x;
    const int b = bs >> 10;
    const int s = bs & 1023;

    __shared__ float yc[CONVDIM];
    __shared__ float rn[H_];
    __shared__ float fms[H_];

    const float* hrow = g_h + (size_t)bs * HTOT;

    for (int c = threadIdx.x; c < CONVDIM; c += 256) {
        const float4 w4 = *(const float4*)(cw + c * 4);
        float acc = cb[c];
        if (s >= 3) acc += hrow[-3 * HTOT + c] * w4.x;
        if (s >= 2) acc += hrow[-2 * HTOT + c] * w4.y;
        if (s >= 1) acc += hrow[-1 * HTOT + c] * w4.z;
        acc += hrow[c] * w4.w;
        yc[c] = acc * sigmoidf_(acc);
    }
    __syncthreads();

    const int wid = threadIdx.x >> 5;
    const int lane = threadIdx.x & 31;
    {
        float a = yc[512 + wid * 64 + lane];
        float b2 = yc[512 + wid * 64 + 32 + lane];
        float ss = a * a + b2 * b2;
#pragma unroll
        for (int o = 16; o; o >>= 1) ss += __shfl_xor_sync(0xffffffffu, ss, o);
        if (lane == 0) {
            rn[wid] = rsqrtf(ss + 1e-12f);
            fms[wid] = 2.f * sigmoidf_(fm[wid]);
        }
    }
    __syncthreads();

    for (int c = threadIdx.x; c < CONVDIM; c += 256) {
        float val = yc[c];
        if (c < 512) {
            int hd = c >> 6, dk = c & 63;
            g_q[((size_t)(b * H_ + hd) * S_ + s) * DK_ + dk] = val;
        } else if (c < 1024) {
            int cc = c - 512; int hd = cc >> 6, dk = cc & 63;
            g_k[((size_t)(b * H_ + hd) * S_ + s) * DK_ + dk] = val * rn[hd];
        } else if (c < 2048) {
            int cc = c - 1024; int hd = cc >> 7, dv = cc & 127;
            g_v[((size_t)(b * H_ + hd) * S_ + s) * DV_ + dv] = val;
        } else {
            int cc = c - 2048; int hd = cc >> 6, dk = cc & 63;
            float fv = fms[hd] * (val + fb[hd * DK_ + dk]);
            g_g[((size_t)(b * H_ + hd) * S_ + s) * DK_ + dk] = sigmoidf_(fv);
        }
    }
}

/* ------------------------------------------------------------------ */
/* recurrent scan v5 (unchanged, passing): tensor-core split-W        */
/* ------------------------------------------------------------------ */
#define SPITCH 132

__global__ void __launch_bounds__(256, 1)
scan_kernel(const float* __restrict__ W)
{
    __shared__ float Ssm[2][16][SPITCH];

    const int bh = blockIdx.y;
    const int kg = blockIdx.x;
    const int h  = bh & 7;
    const int tid  = threadIdx.x;
    const int lane = tid & 31;
    const int wrp  = tid >> 5;
    const int wn   = wrp * 16;

    const int r1 = lane >> 2;
    const int lq = lane & 3;

    const float* Wh = W + (size_t)h * DV_ * DV_;
    unsigned bhi[16][2][2], blo[16][2][2];
#pragma unroll
    for (int kt = 0; kt < 16; kt++) {
#pragma unroll
        for (int nt = 0; nt < 2; nt++) {
            int u0 = kt * 8 + lq;
            int w  = wn + nt * 8 + r1;
            float w0 = Wh[(size_t)u0 * DV_ + w];
            float w1 = Wh[(size_t)(u0 + 4) * DV_ + w];
            unsigned h0 = tf32_(w0), h1 = tf32_(w1);
            bhi[kt][nt][0] = h0;
            bhi[kt][nt][1] = h1;
            blo[kt][nt][0] = tf32_(w0 - __uint_as_float(h0));
            blo[kt][nt][1] = tf32_(w1 - __uint_as_float(h1));
        }
    }

    for (int i = tid; i < 2 * 16 * SPITCH; i += 256)
        ((float*)Ssm)[i] = 0.f;
    __syncthreads();

    float sreg[2][4];
#pragma unroll
    for (int nt = 0; nt < 2; nt++) {
#pragma unroll
        for (int i = 0; i < 4; i++) sreg[nt][i] = 0.f;
    }

    const float* qp = g_q + ((size_t)bh * S_) * DK_ + kg * 16;
    const float* kp = g_k + ((size_t)bh * S_) * DK_ + kg * 16;
    const float* gp = g_g + ((size_t)bh * S_) * DK_ + kg * 16;
    const float* vp = g_v + ((size_t)bh * S_) * DV_ + wn + lq * 2;
    float* yo = g_yp + ((size_t)(kg * BH_ + bh) * S_) * DV_ + wn + lq * 2;

    float q1 = qp[r1], q2 = qp[r1 + 8];
    float k1 = kp[r1], k2 = kp[r1 + 8];
    float gg1 = gp[r1], gg2 = gp[r1 + 8];
    float2 vc[2];
#pragma unroll
    for (int nt = 0; nt < 2; nt++) vc[nt] = *(const float2*)(vp + nt * 8);

    int cur = 0;

    for (int t = 0; t < S_; t++) {
        const int tn = (t + 1 < S_) ? (t + 1) : t;
        float qn1 = qp[tn * DK_ + r1], qn2 = qp[tn * DK_ + r1 + 8];
        float kn1 = kp[tn * DK_ + r1], kn2 = kp[tn * DK_ + r1 + 8];
        float gn1 = gp[tn * DK_ + r1], gn2 = gp[tn * DK_ + r1 + 8];
        float2 vn[2];
#pragma unroll
        for (int nt = 0; nt < 2; nt++)
            vn[nt] = *(const float2*)(vp + tn * DV_ + nt * 8);

        float acc[2][4];
#pragma unroll
        for (int nt = 0; nt < 2; nt++) {
            acc[nt][0] = vc[nt].x; acc[nt][1] = vc[nt].y;
            acc[nt][2] = vc[nt].x; acc[nt][3] = vc[nt].y;
        }

        const float(*Sb)[SPITCH] = Ssm[cur];
#pragma unroll
        for (int kt = 0; kt < 16; kt++) {
            int kc = kt * 8 + lq;
            unsigned a0 = __float_as_uint(Sb[r1][kc]);
            unsigned a1 = __float_as_uint(Sb[r1 + 8][kc]);
            unsigned a2 = __float_as_uint(Sb[r1][kc + 4]);
            unsigned a3 = __float_as_uint(Sb[r1 + 8][kc + 4]);
#pragma unroll
            for (int nt = 0; nt < 2; nt++) {
                asm volatile(
                    "mma.sync.aligned.m16n8k8.row.col.f32.tf32.tf32.f32 "
                    "{%0,%1,%2,%3}, {%4,%5,%6,%7}, {%8,%9}, {%0,%1,%2,%3};"
                    : "+f"(acc[nt][0]), "+f"(acc[nt][1]),
                      "+f"(acc[nt][2]), "+f"(acc[nt][3])
                    : "r"(a0), "r"(a1), "r"(a2), "r"(a3),
                      "r"(bhi[kt][nt][0]), "r"(bhi[kt][nt][1]));
                asm volatile(
                    "mma.sync.aligned.m16n8k8.row.col.f32.tf32.tf32.f32 "
                    "{%0,%1,%2,%3}, {%4,%5,%6,%7}, {%8,%9}, {%0,%1,%2,%3};"
                    : "+f"(acc[nt][0]), "+f"(acc[nt][1]),
                      "+f"(acc[nt][2]), "+f"(acc[nt][3])
                    : "r"(a0), "r"(a1), "r"(a2), "r"(a3),
                      "r"(blo[kt][nt][0]), "r"(blo[kt][nt][1]));
            }
        }

        float(*Sn)[SPITCH] = Ssm[cur ^ 1];
        float y0t[2], y1t[2];
#pragma unroll
        for (int nt = 0; nt < 2; nt++) {
            int col = wn + nt * 8 + lq * 2;
            float s00 = fmaf(gg1, sreg[nt][0], k1 * tanh_fast_(acc[nt][0]));
            float s01 = fmaf(gg1, sreg[nt][1], k1 * tanh_fast_(acc[nt][1]));
            float s10 = fmaf(gg2, sreg[nt][2], k2 * tanh_fast_(acc[nt][2]));
            float s11 = fmaf(gg2, sreg[nt][3], k2 * tanh_fast_(acc[nt][3]));
            sreg[nt][0] = s00; sreg[nt][1] = s01;
            sreg[nt][2] = s10; sreg[nt][3] = s11;
            *(float2*)&Sn[r1][col] = make_float2(
                __uint_as_float(tf32_(s00)), __uint_as_float(tf32_(s01)));
            *(float2*)&Sn[r1 + 8][col] = make_float2(
                __uint_as_float(tf32_(s10)), __uint_as_float(tf32_(s11)));
            y0t[nt] = fmaf(q1, s00, q2 * s10);
            y1t[nt] = fmaf(q1, s01, q2 * s11);
        }
#pragma unroll
        for (int o = 4; o <= 16; o <<= 1) {
#pragma unroll
            for (int nt = 0; nt < 2; nt++) {
                y0t[nt] += __shfl_xor_sync(0xffffffffu, y0t[nt], o);
                y1t[nt] += __shfl_xor_sync(0xffffffffu, y1t[nt], o);
            }
        }
        if (lane < 4) {
#pragma unroll
            for (int nt = 0; nt < 2; nt++)
                *(float2*)(yo + (size_t)t * DV_ + nt * 8) =
                    make_float2(y0t[nt], y1t[nt]);
        }

        __syncthreads();
        cur ^= 1;
        q1 = qn1; q2 = qn2; k1 = kn1; k2 = kn2; gg1 = gn1; gg2 = gn2;
#pragma unroll
        for (int nt = 0; nt < 2; nt++) vc[nt] = vn[nt];
    }
}

/* ------------------------------------------------------------------ */
/* reduce partials + v*D + gate*silu + RMSNorm*g_w (tf32-rounded out) */
/* ------------------------------------------------------------------ */
__global__ void __launch_bounds__(256)
mix_kernel(const float* __restrict__ Dm, const float* __restrict__ gw)
{
    const int bs = blockIdx.x;
    const int b = bs >> 10;
    const int s = bs & 1023;

    __shared__ float ybuf[GDIM];
    __shared__ float red[8];

    float local = 0.f;
    for (int c = threadIdx.x; c < GDIM; c += 256) {
        int hd = c >> 7, dv = c & 127;
        size_t bh = (size_t)b * H_ + hd;
        float acc = 0.f;
#pragma unroll
        for (int kg = 0; kg < KGROUPS; kg++)
            acc += g_yp[(((size_t)kg * BH_ + bh) * S_ + s) * DV_ + dv];
        float vv = g_v[(bh * S_ + s) * DV_ + dv];
        acc = fmaf(vv, Dm[hd * DV_ + dv], acc);
        float gt = g_h[(size_t)bs * HTOT + CONVDIM + c];
        acc *= gt * sigmoidf_(gt);
        ybuf[c] = acc;
        local = fmaf(acc, acc, local);
    }
#pragma unroll
    for (int o = 16; o; o >>= 1) local += __shfl_xor_sync(0xffffffffu, local, o);
    if ((threadIdx.x & 31) == 0) red[threadIdx.x >> 5] = local;
    __syncthreads();
    if (threadIdx.x == 0) {
        float tot = 0.f;
#pragma unroll
        for (int i = 0; i < 8; i++) tot += red[i];
        red[0] = rsqrtf(tot / (float)GDIM + 1e-6f);
    }
    __syncthreads();
    float rms = red[0];
    for (int c = threadIdx.x; c < GDIM; c += 256)
        g_y2[(size_t)bs * GDIM + c] =
            __uint_as_float(tf32_(ybuf[c] * rms * gw[c]));
}

/* ------------------------------------------------------------------ */
extern "C" void kernel_launch(void* const* d_in, const int* in_sizes, int n_in,
                              void* d_out, int out_size)
{
    const float* x    = (const float*)d_in[0];
    const float* w_in = (const float*)d_in[1];
    const float* b_in = (const float*)d_in[2];
    const float* cw   = (const float*)d_in[3];
    const float* cb   = (const float*)d_in[4];
    const float* Dm   = (const float*)d_in[5];
    const float* Wst  = (const float*)d_in[6];
    const float* fm   = (const float*)d_in[7];
    const float* fb   = (const float*)d_in[8];
    const float* gw   = (const float*)d_in[9];
    const float* wout = (const float*)d_in[10];
    float* out = (float*)d_out;

    void *ph = 0, *py2 = 0, *pxr = 0, *pwr = 0, *pwor = 0;
    cudaGetSymbolAddress(&ph,  g_h);
    cudaGetSymbolAddress(&py2, g_y2);
    cudaGetSymbolAddress(&pxr, g_xr);
    cudaGetSymbolAddress(&pwr, g_wr);
    cudaGetSymbolAddress(&pwor, g_wor);

    cudaFuncSetAttribute(gemm_tf32, cudaFuncAttributeMaxDynamicSharedMemorySize,
                         GEMM_SMEM);

    /* 0. tf32 pre-round GEMM operands */
    round_tf32_kernel<<<(MTOT * DIN) / 1024, 256>>>(x, (float*)pxr, MTOT * DIN);
    round_tf32_kernel<<<(HTOT * DIN) / 1024, 256>>>(w_in, (float*)pwr, HTOT * DIN);
    round_tf32_kernel<<<(DOUT * GDIM) / 1024, 256>>>(wout, (float*)pwor, DOUT * GDIM);

    /* 1. in-projection (tf32 mma.sync + cp.async, 2 CTA/SM) */
    gemm_tf32<<<dim3(HTOT / 128, MTOT / 128), 512, GEMM_SMEM>>>(
        (const float*)pxr, (const float*)pwr, b_in, (float*)ph,
        MTOT, HTOT, DIN, 1);
    /* 2. conv + silu + split + knorm + gate precompute */
    conv_split_kernel<<<MTOT, 256>>>(cw, cb, fm, fb);
    /* 3. recurrent scan (tensor-core, split-W) */
    scan_kernel<<<dim3(KGROUPS, BH_), 256>>>(Wst);
    /* 4. reduce + v*D + gate + RMSNorm (tf32-rounded y2) */
    mix_kernel<<<MTOT, 256>>>(Dm, gw);
    /* 5. out-projection (tf32 mma.sync + cp.async, 2 CTA/SM) */
    gemm_tf32<<<dim3(DOUT / 128, MTOT / 128), 512, GEMM_SMEM>>>(
        (const float*)py2, (const float*)pwor, 0, out,
        MTOT, DOUT, GDIM, 0);
}